// round 2
// baseline (speedup 1.0000x reference)
#include <cuda_runtime.h>

#define HDIM 2048
#define NTHREADS 1024
#define MAXS 1000

// ---------------- threefry2x32 (JAX), key = (0, 42) ----------------
__device__ __forceinline__ void threefry2x32(unsigned k1, unsigned k2,
                                             unsigned x0, unsigned x1,
                                             unsigned* o0, unsigned* o1) {
    unsigned ks0 = k1, ks1 = k2, ks2 = k1 ^ k2 ^ 0x1BD11BDAu;
    x0 += ks0; x1 += ks1;
#define TF_R(r) { x0 += x1; x1 = (x1 << (r)) | (x1 >> (32 - (r))); x1 ^= x0; }
    TF_R(13) TF_R(15) TF_R(26) TF_R(6)   x0 += ks1; x1 += ks2 + 1u;
    TF_R(17) TF_R(29) TF_R(16) TF_R(24)  x0 += ks2; x1 += ks0 + 2u;
    TF_R(13) TF_R(15) TF_R(26) TF_R(6)   x0 += ks0; x1 += ks1 + 3u;
    TF_R(17) TF_R(29) TF_R(16) TF_R(24)  x0 += ks1; x1 += ks2 + 4u;
    TF_R(13) TF_R(15) TF_R(26) TF_R(6)   x0 += ks2; x1 += ks0 + 5u;
#undef TF_R
    *o0 = x0; *o1 = x1;
}

// XLA ErfInv32 (Giles) polynomial — matches lax.erf_inv on f32.
__device__ __forceinline__ float erfinv_xla(float x) {
    float w = -logf((1.0f - x) * (1.0f + x));
    float p;
    if (w < 5.0f) {
        w -= 2.5f;
        p = 2.81022636e-08f;
        p = fmaf(p, w, 3.43273939e-07f);
        p = fmaf(p, w, -3.5233877e-06f);
        p = fmaf(p, w, -4.39150654e-06f);
        p = fmaf(p, w, 0.00021858087f);
        p = fmaf(p, w, -0.00125372503f);
        p = fmaf(p, w, -0.00417768164f);
        p = fmaf(p, w, 0.246640727f);
        p = fmaf(p, w, 1.50140941f);
    } else {
        w = sqrtf(w) - 3.0f;
        p = -0.000200214257f;
        p = fmaf(p, w, 0.000100950558f);
        p = fmaf(p, w, 0.00134934322f);
        p = fmaf(p, w, -0.00367342844f);
        p = fmaf(p, w, 0.00573950773f);
        p = fmaf(p, w, -0.0076224613f);
        p = fmaf(p, w, 0.00943887047f);
        p = fmaf(p, w, 1.00167406f);
        p = fmaf(p, w, 2.83297682f);
    }
    return p * x;
}

// JAX normal from 32 raw bits: uniform in [nextafter(-1,0), 1), then sqrt(2)*erfinv.
__device__ __forceinline__ float bits_to_normal(unsigned bits) {
    const float lo = -0.99999994f;            // nextafterf(-1, 0)
    const float span = 1.0f - lo;             // f32(1 - lo)
    float f = __uint_as_float((bits >> 9) | 0x3f800000u) - 1.0f;  // [0,1)
    float u = fmaxf(lo, f * span + lo);
    return 1.41421356f * erfinv_xla(u);
}

__device__ __forceinline__ float sigmoidf_(float x) {
    return 1.0f / (1.0f + expf(-x));
}

__global__ void __launch_bounds__(NTHREADS, 1)
sketch_decoder_kernel(const float* __restrict__ W_ih,
                      const float* __restrict__ b_ih,
                      const float* __restrict__ b_hh,
                      const float* __restrict__ W_lin,
                      const float* __restrict__ b_lin,
                      const int*   __restrict__ msp,
                      float* __restrict__ out) {
    __shared__ float s_last[5];
    __shared__ float s_part[32][8];   // padded to 8 to dodge bank conflicts
    __shared__ float s_red[8];
    __shared__ float s_blin[8];
    __shared__ int   s_done;
    __shared__ float s_eps[MAXS][2];

    const int tid = threadIdx.x;
    int ms = msp[0];
    if (ms < 0) ms = 0;
    if (ms > MAXS) ms = MAXS;

    // ---- init output buffer: row0 = [0,0,1,0,0], rest = [0,0,0,0,1] ----
    for (int idx = tid; idx < ms * 5; idx += NTHREADS) {
        int r = idx / 5, c = idx - r * 5;
        float v = (r == 0) ? ((c == 2) ? 1.0f : 0.0f)
                           : ((c == 4) ? 1.0f : 0.0f);
        out[idx] = v;
    }

    // ---- precompute eps (JAX partitionable threefry, key(42)) ----
    // flat index m in the (ms,2) array encrypts 64-bit counter m: (hi=0, lo=m);
    // 32-bit draw = x0out ^ x1out.
    for (int i = tid; i < ms; i += NTHREADS) {
        #pragma unroll
        for (int c = 0; c < 2; c++) {
            unsigned m = (unsigned)(2 * i + c);
            unsigned r0, r1;
            threefry2x32(0u, 42u, 0u, m, &r0, &r1);
            s_eps[i][c] = bits_to_normal(r0 ^ r1);
        }
    }

    if (tid == 0) {
        s_last[0] = 0.0f; s_last[1] = 0.0f; s_last[2] = 1.0f;
        s_last[3] = 0.0f; s_last[4] = 0.0f;
        s_done = 0;
    }
    if (tid < 7) s_blin[tid] = b_lin[tid];

    // ---- per-thread constants: combined biases for the 3 live gate rows ----
    const int j0 = tid, j1 = tid + NTHREADS;
    const float bsi0 = b_ih[j0]            + b_hh[j0];
    const float bsg0 = b_ih[2 * HDIM + j0] + b_hh[2 * HDIM + j0];
    const float bso0 = b_ih[3 * HDIM + j0] + b_hh[3 * HDIM + j0];
    const float bsi1 = b_ih[j1]            + b_hh[j1];
    const float bsg1 = b_ih[2 * HDIM + j1] + b_hh[2 * HDIM + j1];
    const float bso1 = b_ih[3 * HDIM + j1] + b_hh[3 * HDIM + j1];

    __syncthreads();

    const int warp = tid >> 5, lane = tid & 31;
    int n = 1;

    for (int i = 0; i < ms; i++) {
        const float l0 = s_last[0], l1 = s_last[1], l2 = s_last[2],
                    l3 = s_last[3], l4 = s_last[4];

        float acc[7];
        #pragma unroll
        for (int k = 0; k < 7; k++) acc[k] = 0.0f;

        // ---- element j0 ----
        {
            const float* wi = W_ih + j0 * 5;
            const float* wg = W_ih + (2 * HDIM + j0) * 5;
            const float* wo = W_ih + (3 * HDIM + j0) * 5;
            float ig = fmaf(wi[4], l4, fmaf(wi[3], l3, fmaf(wi[2], l2, fmaf(wi[1], l1, fmaf(wi[0], l0, bsi0)))));
            float gg = fmaf(wg[4], l4, fmaf(wg[3], l3, fmaf(wg[2], l2, fmaf(wg[1], l1, fmaf(wg[0], l0, bsg0)))));
            float og = fmaf(wo[4], l4, fmaf(wo[3], l3, fmaf(wo[2], l2, fmaf(wo[1], l1, fmaf(wo[0], l0, bso0)))));
            float cc = sigmoidf_(ig) * tanhf(gg);
            float h  = sigmoidf_(og) * tanhf(cc);
            #pragma unroll
            for (int k = 0; k < 7; k++)
                acc[k] = fmaf(W_lin[k * HDIM + j0], h, acc[k]);
        }
        // ---- element j1 ----
        {
            const float* wi = W_ih + j1 * 5;
            const float* wg = W_ih + (2 * HDIM + j1) * 5;
            const float* wo = W_ih + (3 * HDIM + j1) * 5;
            float ig = fmaf(wi[4], l4, fmaf(wi[3], l3, fmaf(wi[2], l2, fmaf(wi[1], l1, fmaf(wi[0], l0, bsi1)))));
            float gg = fmaf(wg[4], l4, fmaf(wg[3], l3, fmaf(wg[2], l2, fmaf(wg[1], l1, fmaf(wg[0], l0, bsg1)))));
            float og = fmaf(wo[4], l4, fmaf(wo[3], l3, fmaf(wo[2], l2, fmaf(wo[1], l1, fmaf(wo[0], l0, bso1)))));
            float cc = sigmoidf_(ig) * tanhf(gg);
            float h  = sigmoidf_(og) * tanhf(cc);
            #pragma unroll
            for (int k = 0; k < 7; k++)
                acc[k] = fmaf(W_lin[k * HDIM + j1], h, acc[k]);
        }

        // ---- warp reduce 7 accumulators ----
        #pragma unroll
        for (int k = 0; k < 7; k++) {
            #pragma unroll
            for (int off = 16; off > 0; off >>= 1)
                acc[k] += __shfl_down_sync(0xffffffffu, acc[k], off);
        }
        if (lane == 0) {
            #pragma unroll
            for (int k = 0; k < 7; k++) s_part[warp][k] = acc[k];
        }
        __syncthreads();

        // ---- cross-warp reduce + scalar tail (warp 0) ----
        if (warp == 0) {
            if (lane < 7) {
                float s = 0.0f;
                #pragma unroll
                for (int w = 0; w < 32; w++) s += s_part[w][lane];
                s_red[lane] = s;
            }
            __syncwarp();
            if (lane == 0 && i > 0) {
                float o[7];
                #pragma unroll
                for (int k = 0; k < 7; k++) o[k] = tanhf(s_red[k] + s_blin[k]);
                float sig_x = expf(o[1] * 0.5f);
                float sig_y = expf(o[3] * 0.5f);
                float mx = fmaxf(o[4], fmaxf(o[5], o[6]));
                float e0 = expf(o[4] - mx), e1 = expf(o[5] - mx), e2 = expf(o[6] - mx);
                float inv = 1.0f / (e0 + e1 + e2);
                float sm0 = e0 * inv, sm1 = e1 * inv, sm2 = e2 * inv;
                float sx = o[0] + sig_x * s_eps[i][0];
                float sy = o[2] + sig_y * s_eps[i][1];
                float* row = out + n * 5;
                row[0] = sx; row[1] = sy; row[2] = sm0; row[3] = sm1; row[4] = sm2;
                s_last[0] = sx; s_last[1] = sy;
                s_last[2] = sm0; s_last[3] = sm1; s_last[4] = sm2;
                n++;
                // argmax(new_row[2:]) == 2  <=>  sm2 strictly greater than both
                if (sm2 > sm0 && sm2 > sm1) s_done = 1;
            }
        }
        __syncthreads();
        if (s_done) break;   // all remaining steps are provable no-ops
    }
}

extern "C" void kernel_launch(void* const* d_in, const int* in_sizes, int n_in,
                              void* d_out, int out_size) {
    const float* W_ih  = (const float*)d_in[0];
    // d_in[1] = W_hh: multiplied by a provably-zero hidden state -> unused.
    const float* b_ih  = (const float*)d_in[2];
    const float* b_hh  = (const float*)d_in[3];
    const float* W_lin = (const float*)d_in[4];
    const float* b_lin = (const float*)d_in[5];
    const int*   msp   = (const int*)d_in[6];
    float* out = (float*)d_out;

    sketch_decoder_kernel<<<1, NTHREADS>>>(W_ih, b_ih, b_hh, W_lin, b_lin, msp, out);
    (void)in_sizes; (void)n_in; (void)out_size;
}

// round 4
// speedup vs baseline: 3.0252x; 3.0252x over previous
#include <cuda_runtime.h>

#define HDIM 2048
#define NT 256
#define MAXS 1000

typedef unsigned long long ull;

// ---------------- packed f32x2 helpers ----------------
__device__ __forceinline__ ull pk2(float lo, float hi) {
    ull r; asm("mov.b64 %0, {%1,%2};" : "=l"(r) : "f"(lo), "f"(hi)); return r;
}
__device__ __forceinline__ void upk2(ull v, float& lo, float& hi) {
    asm("mov.b64 {%0,%1}, %2;" : "=f"(lo), "=f"(hi) : "l"(v));
}
__device__ __forceinline__ ull fma2_(ull a, ull b, ull c) {
    ull d; asm("fma.rn.f32x2 %0, %1, %2, %3;" : "=l"(d) : "l"(a), "l"(b), "l"(c)); return d;
}
__device__ __forceinline__ float tanha(float x) {
    float y; asm("tanh.approx.f32 %0, %1;" : "=f"(y) : "f"(x)); return y;
}

// ---------------- threefry2x32 (JAX), key = (0, 42) ----------------
__device__ __forceinline__ void threefry2x32(unsigned k1, unsigned k2,
                                             unsigned x0, unsigned x1,
                                             unsigned* o0, unsigned* o1) {
    unsigned ks0 = k1, ks1 = k2, ks2 = k1 ^ k2 ^ 0x1BD11BDAu;
    x0 += ks0; x1 += ks1;
#define TF_R(r) { x0 += x1; x1 = (x1 << (r)) | (x1 >> (32 - (r))); x1 ^= x0; }
    TF_R(13) TF_R(15) TF_R(26) TF_R(6)   x0 += ks1; x1 += ks2 + 1u;
    TF_R(17) TF_R(29) TF_R(16) TF_R(24)  x0 += ks2; x1 += ks0 + 2u;
    TF_R(13) TF_R(15) TF_R(26) TF_R(6)   x0 += ks0; x1 += ks1 + 3u;
    TF_R(17) TF_R(29) TF_R(16) TF_R(24)  x0 += ks1; x1 += ks2 + 4u;
    TF_R(13) TF_R(15) TF_R(26) TF_R(6)   x0 += ks2; x1 += ks0 + 5u;
#undef TF_R
    *o0 = x0; *o1 = x1;
}

// XLA ErfInv32 (Giles) polynomial — matches lax.erf_inv on f32.
__device__ __forceinline__ float erfinv_xla(float x) {
    float w = -logf((1.0f - x) * (1.0f + x));
    float p;
    if (w < 5.0f) {
        w -= 2.5f;
        p = 2.81022636e-08f;
        p = fmaf(p, w, 3.43273939e-07f);
        p = fmaf(p, w, -3.5233877e-06f);
        p = fmaf(p, w, -4.39150654e-06f);
        p = fmaf(p, w, 0.00021858087f);
        p = fmaf(p, w, -0.00125372503f);
        p = fmaf(p, w, -0.00417768164f);
        p = fmaf(p, w, 0.246640727f);
        p = fmaf(p, w, 1.50140941f);
    } else {
        w = sqrtf(w) - 3.0f;
        p = -0.000200214257f;
        p = fmaf(p, w, 0.000100950558f);
        p = fmaf(p, w, 0.00134934322f);
        p = fmaf(p, w, -0.00367342844f);
        p = fmaf(p, w, 0.00573950773f);
        p = fmaf(p, w, -0.0076224613f);
        p = fmaf(p, w, 0.00943887047f);
        p = fmaf(p, w, 1.00167406f);
        p = fmaf(p, w, 2.83297682f);
    }
    return p * x;
}

__device__ __forceinline__ float bits_to_normal(unsigned bits) {
    const float lo = -0.99999994f;            // nextafterf(-1, 0)
    const float span = 1.0f - lo;
    float f = __uint_as_float((bits >> 9) | 0x3f800000u) - 1.0f;  // [0,1)
    float u = fmaxf(lo, f * span + lo);
    return 1.41421356f * erfinv_xla(u);
}

__global__ void __launch_bounds__(NT, 1)
sketch_decoder_kernel(const float* __restrict__ W_ih,
                      const float* __restrict__ b_ih,
                      const float* __restrict__ b_hh,
                      const float* __restrict__ W_lin,
                      const float* __restrict__ b_lin,
                      const int*   __restrict__ msp,
                      float* __restrict__ out) {
    __shared__ float  s_acc[7][NT];
    __shared__ float  s_last[5];
    __shared__ float  s_red[7];
    __shared__ float  s_blin[7];
    __shared__ int    s_done;
    __shared__ float2 s_eps[MAXS];

    const int tid = threadIdx.x;
    int ms = msp[0];
    if (ms < 0) ms = 0;
    if (ms > MAXS) ms = MAXS;

    // ---- init output buffer: row0 = [0,0,1,0,0], rest = [0,0,0,0,1] ----
    for (int idx = tid; idx < ms * 5; idx += NT) {
        int r = idx / 5, c = idx - r * 5;
        out[idx] = (r == 0) ? ((c == 2) ? 1.0f : 0.0f)
                            : ((c == 4) ? 1.0f : 0.0f);
    }

    // ---- precompute eps (JAX partitionable threefry, key(42)) ----
    for (int i = tid; i < ms; i += NT) {
        unsigned r0, r1;
        threefry2x32(0u, 42u, 0u, (unsigned)(2 * i), &r0, &r1);
        float ex = bits_to_normal(r0 ^ r1);
        threefry2x32(0u, 42u, 0u, (unsigned)(2 * i + 1), &r0, &r1);
        float ey = bits_to_normal(r0 ^ r1);
        s_eps[i] = make_float2(ex, ey);
    }

    if (tid == 0) {
        s_last[0] = 0.0f; s_last[1] = 0.0f; s_last[2] = 1.0f;
        s_last[3] = 0.0f; s_last[4] = 0.0f;
        s_done = 0;
    }
    if (tid < 7) s_blin[tid] = b_lin[tid];

    // ---- register-resident packed weights (8 elements / thread = 4 pairs) ----
    // i and o gate rows pre-scaled by 0.5 (sigmoid via 0.5*tanh(0.5x)+0.5).
    ull wi[4][5], wg[4][5], wo[4][5], wl[4][7], bi[4], bg[4], bo[4];
    #pragma unroll
    for (int q = 0; q < 4; q++) {
        const int elo = tid + (2 * q) * NT;
        const int ehi = elo + NT;
        const int gl = 2 * HDIM + elo, gh = 2 * HDIM + ehi;
        const int ol = 3 * HDIM + elo, oh = 3 * HDIM + ehi;
        #pragma unroll
        for (int c = 0; c < 5; c++) {
            wi[q][c] = pk2(0.5f * W_ih[elo * 5 + c], 0.5f * W_ih[ehi * 5 + c]);
            wg[q][c] = pk2(W_ih[gl * 5 + c],          W_ih[gh * 5 + c]);
            wo[q][c] = pk2(0.5f * W_ih[ol * 5 + c],  0.5f * W_ih[oh * 5 + c]);
        }
        bi[q] = pk2(0.5f * (b_ih[elo] + b_hh[elo]), 0.5f * (b_ih[ehi] + b_hh[ehi]));
        bg[q] = pk2(b_ih[gl] + b_hh[gl],            b_ih[gh] + b_hh[gh]);
        bo[q] = pk2(0.5f * (b_ih[ol] + b_hh[ol]),   0.5f * (b_ih[oh] + b_hh[oh]));
        #pragma unroll
        for (int k = 0; k < 7; k++)
            wl[q][k] = pk2(W_lin[k * HDIM + elo], W_lin[k * HDIM + ehi]);
    }

    __syncthreads();

    const int warp = tid >> 5, lane = tid & 31;

    // step 0 of the reference is a provable no-op (write gated by i>0) -> start at 1
    for (int i = 1; i < ms; i++) {
        ull lp[5];
        #pragma unroll
        for (int c = 0; c < 5; c++) { float v = s_last[c]; lp[c] = pk2(v, v); }

        ull acc[7];
        #pragma unroll
        for (int k = 0; k < 7; k++) acc[k] = 0ull;

        #pragma unroll
        for (int q = 0; q < 4; q++) {
            ull gi = bi[q], gg = bg[q], go = bo[q];
            #pragma unroll
            for (int c = 0; c < 5; c++) {
                gi = fma2_(wi[q][c], lp[c], gi);
                gg = fma2_(wg[q][c], lp[c], gg);
                go = fma2_(wo[q][c], lp[c], go);
            }
            float i0, i1, g0, g1, o0, o1;
            upk2(gi, i0, i1); upk2(gg, g0, g1); upk2(go, o0, o1);
            // sigmoid(x) = 0.5*tanh(0.5x)+0.5 ; 0.5 already folded into gi/go
            float si0 = fmaf(tanha(i0), 0.5f, 0.5f);
            float si1 = fmaf(tanha(i1), 0.5f, 0.5f);
            float c0 = si0 * tanha(g0);
            float c1 = si1 * tanha(g1);
            float so0 = fmaf(tanha(o0), 0.5f, 0.5f);
            float so1 = fmaf(tanha(o1), 0.5f, 0.5f);
            float h0 = so0 * tanha(c0);
            float h1 = so1 * tanha(c1);
            ull hp = pk2(h0, h1);
            #pragma unroll
            for (int k = 0; k < 7; k++)
                acc[k] = fma2_(wl[q][k], hp, acc[k]);
        }

        #pragma unroll
        for (int k = 0; k < 7; k++) {
            float a0, a1; upk2(acc[k], a0, a1);
            s_acc[k][tid] = a0 + a1;
        }
        __syncthreads();

        // 7 warps each reduce one output k (conflict-free column reads)
        if (warp < 7) {
            float s = s_acc[warp][lane];
            #pragma unroll
            for (int m = 1; m < 8; m++) s += s_acc[warp][lane + m * 32];
            #pragma unroll
            for (int off = 16; off > 0; off >>= 1)
                s += __shfl_down_sync(0xffffffffu, s, off);
            if (lane == 0) s_red[warp] = tanhf(s + s_blin[warp]);  // accurate tanh at output
        }
        __syncthreads();

        // scalar tail
        if (tid == 0) {
            float o0 = s_red[0], o1 = s_red[1], o2 = s_red[2], o3 = s_red[3];
            float o4 = s_red[4], o5 = s_red[5], o6 = s_red[6];
            float sig_x = __expf(o1 * 0.5f);
            float sig_y = __expf(o3 * 0.5f);
            float mx = fmaxf(o4, fmaxf(o5, o6));
            float e0 = __expf(o4 - mx), e1 = __expf(o5 - mx), e2 = __expf(o6 - mx);
            float inv = __fdividef(1.0f, e0 + e1 + e2);
            float sm0 = e0 * inv, sm1 = e1 * inv, sm2 = e2 * inv;
            float2 ep = s_eps[i];
            float sx = fmaf(sig_x, ep.x, o0);
            float sy = fmaf(sig_y, ep.y, o2);
            float* row = out + i * 5;   // n == i until termination
            row[0] = sx; row[1] = sy; row[2] = sm0; row[3] = sm1; row[4] = sm2;
            s_last[0] = sx; s_last[1] = sy;
            s_last[2] = sm0; s_last[3] = sm1; s_last[4] = sm2;
            // argmax(row[2:]) == 2  <=>  sm2 strictly beats both (first-max-wins ties)
            if (sm2 > sm0 && sm2 > sm1) s_done = 1;
        }
        __syncthreads();
        if (s_done) break;   // remaining steps are provable no-ops
    }
}

extern "C" void kernel_launch(void* const* d_in, const int* in_sizes, int n_in,
                              void* d_out, int out_size) {
    const float* W_ih  = (const float*)d_in[0];
    // d_in[1] = W_hh: multiplied by a provably-zero hidden state -> unused.
    const float* b_ih  = (const float*)d_in[2];
    const float* b_hh  = (const float*)d_in[3];
    const float* W_lin = (const float*)d_in[4];
    const float* b_lin = (const float*)d_in[5];
    const int*   msp   = (const int*)d_in[6];
    float* out = (float*)d_out;

    sketch_decoder_kernel<<<1, NT>>>(W_ih, b_ih, b_hh, W_lin, b_lin, msp, out);
    (void)in_sizes; (void)n_in; (void)out_size;
}